// round 4
// baseline (speedup 1.0000x reference)
#include <cuda_runtime.h>
#include <math.h>

// ---------------- problem constants ----------------
#define NT       256     // threads per block (8 warps -> 2 per SMSP)
#define BT       16      // batch items per block -> 128 blocks
#define T_STEPS  128
#define STATE    115
#define ACT      39
#define CIN      154     // STATE + ACT
#define COUT     116     // STATE + 1 reward channel

#define SBUF 132         // activation buffer stride
#define SX   116         // x state stride
#define SA   40          // action stride

// ---------------- shared memory layout (float offsets) ----------------
#define OW0   0
#define OW1   2464       // 154*16
#define OW2   2976       // +16*32
#define OW3   5024       // +32*64
#define OW4   13216      // +64*128
#define OW5   21408      // +128*64
#define OW6   23456      // +64*32
#define OW7   23968      // +32*16
#define OW8   24096      // +16*8 ; W8 is 8x116 padded
#define OWR   25024      // Wr padded to 348
#define OB0   25372
#define OB1   25388
#define OB2   25420
#define OB3   25484
#define OB4   25612
#define OB5   25676
#define OB6   25708
#define OB7   25724
#define OB8   25732      // 116 (padded)
#define OBR   25848      // 4
#define OBUFA 25852      // 16*132 = 2112
#define OBUFB 27964      // 2112
#define OXS   30076      // 16*116 = 1856
#define OAB   31932      // 16*40  = 640
#define SMEM_FLOATS 32572
#define SMEM_BYTES  (SMEM_FLOATS * 4)   // 130288 B

struct Params {
    const float* u;
    const float* W[9];
    const float* b[9];
    const float* Wr;
    const float* br;
    float* out;
};

__device__ __forceinline__ void cpy_sh(float* dst, const float* __restrict__ src, int n) {
    for (int k = threadIdx.x; k < n; k += NT) dst[k] = src[k];
}

// Generic register-tiled layer: out[b][o] = act( in[b][:] @ W + bias )
// W: [FI][FO] row-major in SMEM. in/out strides = SBUF. TO in {1,2,4}.
template<int FI, int FO, int TO, int TB, bool CLIP>
__device__ __forceinline__ void layerT(const float* __restrict__ W,
                                       const float* __restrict__ bias,
                                       const float* __restrict__ in,
                                       float* __restrict__ out) {
    constexpr int G = FO / TO;
    constexpr int TILES = G * (BT / TB);
    for (int tile = threadIdx.x; tile < TILES; tile += NT) {
        const int og = tile % G;
        const int bg = tile / G;
        const int o0 = og * TO;
        const float* inp = in + bg * TB * SBUF;
        float acc[TB][TO];
#pragma unroll
        for (int tb = 0; tb < TB; ++tb)
#pragma unroll
            for (int to = 0; to < TO; ++to) acc[tb][to] = bias[o0 + to];
#pragma unroll
        for (int i = 0; i < FI; ++i) {
            float w[TO];
            if constexpr (TO == 4) {
                float4 wv = *(const float4*)(W + i * FO + o0);
                w[0] = wv.x; w[1] = wv.y; w[2] = wv.z; w[3] = wv.w;
            } else if constexpr (TO == 2) {
                float2 wv = *(const float2*)(W + i * FO + o0);
                w[0] = wv.x; w[1] = wv.y;
            } else {
                w[0] = W[i * FO + o0];
            }
#pragma unroll
            for (int tb = 0; tb < TB; ++tb) {
                float v = inp[tb * SBUF + i];
#pragma unroll
                for (int to = 0; to < TO; ++to)
                    acc[tb][to] = fmaf(v, w[to], acc[tb][to]);
            }
        }
#pragma unroll
        for (int tb = 0; tb < TB; ++tb)
#pragma unroll
            for (int to = 0; to < TO; ++to) {
                float r = acc[tb][to];
                if constexpr (CLIP) r = fminf(fmaxf(r, 0.0f), 6.0f);
                out[(bg * TB + tb) * SBUF + o0 + to] = r;
            }
    }
}

__global__ void __launch_bounds__(NT, 1) worldnet_kernel(Params p) {
    extern __shared__ float sh[];
    const int tid = threadIdx.x;
    const int b0 = blockIdx.x * BT;

    // ---- one-time: load all weights/biases into SMEM ----
    cpy_sh(sh + OW0, p.W[0], 154 * 16);
    cpy_sh(sh + OW1, p.W[1], 16 * 32);
    cpy_sh(sh + OW2, p.W[2], 32 * 64);
    cpy_sh(sh + OW3, p.W[3], 64 * 128);
    cpy_sh(sh + OW4, p.W[4], 128 * 64);
    cpy_sh(sh + OW5, p.W[5], 64 * 32);
    cpy_sh(sh + OW6, p.W[6], 32 * 16);
    cpy_sh(sh + OW7, p.W[7], 16 * 8);
    for (int k = tid; k < 8 * 116; k += NT) {           // W8 padded 8x116
        int i = k / 116, o = k - i * 116;
        sh[OW8 + k] = (o < STATE) ? p.W[8][i * STATE + o] : 0.0f;
    }
    for (int k = tid; k < 348; k += NT)                  // Wr padded
        sh[OWR + k] = (k < STATE * 3) ? p.Wr[k] : 0.0f;
    cpy_sh(sh + OB0, p.b[0], 16);
    cpy_sh(sh + OB1, p.b[1], 32);
    cpy_sh(sh + OB2, p.b[2], 64);
    cpy_sh(sh + OB3, p.b[3], 128);
    cpy_sh(sh + OB4, p.b[4], 64);
    cpy_sh(sh + OB5, p.b[5], 32);
    cpy_sh(sh + OB6, p.b[6], 16);
    cpy_sh(sh + OB7, p.b[7], 8);
    for (int k = tid; k < 116; k += NT)
        sh[OB8 + k] = (k < STATE) ? p.b[8][k] : 0.0f;
    for (int k = tid; k < 4; k += NT)
        sh[OBR + k] = (k < 3) ? p.br[k] : 0.0f;

    // ---- init x0 = u[:, 0, :STATE] ----
    for (int k = tid; k < BT * STATE; k += NT) {
        int b = k / STATE, i = k - b * STATE;
        sh[OXS + b * SX + i] = p.u[(size_t)(b0 + b) * T_STEPS * CIN + i];
    }
    __syncthreads();

    // ---- time loop ----
    for (int t = 0; t < T_STEPS; ++t) {
        // stage actions a_t (gmem loads issued first to overlap with the stores)
        for (int k = tid; k < BT * ACT; k += NT) {
            int b = k / ACT, j = k - b * ACT;
            sh[OAB + b * SA + j] =
                p.u[((size_t)(b0 + b) * T_STEPS + t) * CIN + STATE + j];
        }
        // write out[:, t, 0:STATE] = x_t
        for (int k = tid; k < BT * STATE; k += NT) {
            int b = k / STATE, i = k - b * STATE;
            p.out[((size_t)(b0 + b) * T_STEPS + t) * COUT + i] = sh[OXS + b * SX + i];
        }
        __syncthreads();

        // ---- L0: concat(x,a)[154] -> 16, clip. TO=1 -> 256 tiles ----
        {
            const float* W = sh + OW0;
            const float* bias = sh + OB0;
            const int og = tid & 15;       // output neuron
            const int b  = tid >> 4;       // batch item
            float a0 = bias[og];
            const float* xr = sh + OXS + b * SX;
#pragma unroll
            for (int i = 0; i < STATE; ++i)
                a0 = fmaf(xr[i], W[i * 16 + og], a0);
            const float* ar = sh + OAB + b * SA;
#pragma unroll
            for (int j = 0; j < ACT; ++j)
                a0 = fmaf(ar[j], W[(STATE + j) * 16 + og], a0);
            a0 = fminf(fmaxf(a0, 0.0f), 6.0f);
            sh[OBUFB + b * SBUF + og] = a0;
        }
        __syncthreads();

        layerT<16, 32, 2, 1, true >(sh + OW1, sh + OB1, sh + OBUFB, sh + OBUFA); __syncthreads();
        layerT<32, 64, 4, 1, true >(sh + OW2, sh + OB2, sh + OBUFA, sh + OBUFB); __syncthreads();
        layerT<64, 128, 4, 2, true >(sh + OW3, sh + OB3, sh + OBUFB, sh + OBUFA); __syncthreads();
        layerT<128, 64, 4, 1, true >(sh + OW4, sh + OB4, sh + OBUFA, sh + OBUFB); __syncthreads();
        layerT<64, 32, 2, 1, true >(sh + OW5, sh + OB5, sh + OBUFB, sh + OBUFA); __syncthreads();
        layerT<32, 16, 1, 1, true >(sh + OW6, sh + OB6, sh + OBUFA, sh + OBUFB); __syncthreads();
        layerT<16, 8, 1, 1, true >(sh + OW7, sh + OB7, sh + OBUFB, sh + OBUFA); __syncthreads();
        layerT<8, 116, 4, 1, false>(sh + OW8, sh + OB8, sh + OBUFA, sh + OBUFB); __syncthreads();

        // ---- residual: x <- x + delta ----
        for (int k = tid; k < BT * STATE; k += NT) {
            int b = k / STATE, i = k - b * STATE;
            sh[OXS + b * SX + i] += sh[OBUFB + b * SBUF + i];
        }
        __syncthreads();

        // ---- reward from x_{t+1}: 16 lanes per item ----
        {
            int b = tid >> 4;
            int l = tid & 15;
            float p0 = 0.f, p1 = 0.f, p2 = 0.f;
            const float* xr = sh + OXS + b * SX;
            const float* Wr = sh + OWR;
#pragma unroll
            for (int i = l; i < STATE; i += 16) {
                float v = xr[i];
                p0 = fmaf(v, Wr[3 * i + 0], p0);
                p1 = fmaf(v, Wr[3 * i + 1], p1);
                p2 = fmaf(v, Wr[3 * i + 2], p2);
            }
#pragma unroll
            for (int off = 8; off > 0; off >>= 1) {
                p0 += __shfl_down_sync(0xffffffffu, p0, off, 16);
                p1 += __shfl_down_sync(0xffffffffu, p1, off, 16);
                p2 += __shfl_down_sync(0xffffffffu, p2, off, 16);
            }
            if (l == 0) {
                p0 += sh[OBR + 0]; p1 += sh[OBR + 1]; p2 += sh[OBR + 2];
                p.out[((size_t)(b0 + b) * T_STEPS + t) * COUT + STATE] =
                    -sqrtf(p0 * p0 + p1 * p1 + p2 * p2);
            }
        }
        // no barrier needed: next iteration only reads OXS / writes OAB & gmem
    }
}

extern "C" void kernel_launch(void* const* d_in, const int* in_sizes, int n_in,
                              void* d_out, int out_size) {
    Params p;
    p.u = (const float*)d_in[0];
    for (int i = 0; i < 9; ++i) {
        p.W[i] = (const float*)d_in[1 + 2 * i];
        p.b[i] = (const float*)d_in[2 + 2 * i];
    }
    p.Wr = (const float*)d_in[19];
    p.br = (const float*)d_in[20];
    p.out = (float*)d_out;

    cudaFuncSetAttribute(worldnet_kernel,
                         cudaFuncAttributeMaxDynamicSharedMemorySize, SMEM_BYTES);
    worldnet_kernel<<<2048 / BT, NT, SMEM_BYTES>>>(p);
}

// round 5
// speedup vs baseline: 1.1744x; 1.1744x over previous
#include <cuda_runtime.h>
#include <math.h>

// ---------------- problem constants ----------------
#define NT       256     // 8 warps
#define BT       16      // batch items per block -> 128 blocks
#define T_STEPS  128
#define STATE    115
#define ACT      39
#define CIN      154
#define COUT     116

// conflict-free strides (mod-32-bank analysis for 16 batch lanes)
#define SBUF 130         // 130 % 32 = 2  -> 2b distinct for b in [0,16)
#define SX   130
#define SA   33          // odd -> b distinct

// ---------------- shared memory layout (float offsets) ----------------
#define OW0   0          // 154*16 = 2464
#define OW1   2464       // 16*32  = 512
#define OW2   2976       // 32*64  = 2048
#define OW3   5024       // 64*128 = 8192
#define OW4   13216      // 128*64 = 8192
#define OW5   21408      // 64*32  = 2048
#define OW6   23456      // 32*16  = 512
#define OW7   23968      // 16*8   = 128
#define OW8   24096      // 8*128 padded = 1024
#define OWR   25120      // 348 (Wr padded)
#define OB0   25468
#define OB1   25484
#define OB2   25516
#define OB3   25580
#define OB4   25708
#define OB5   25772
#define OB6   25804
#define OB7   25820
#define OB8   25828      // 128 padded
#define OBR   25956      // 4
#define OBUFA 25960      // 16*130 = 2080
#define OBUFB 28040      // 2080
#define OXS   30120      // 16*130 = 2080
#define OAB   32200      // 16*33  = 528
#define SMEM_FLOATS 32728
#define SMEM_BYTES  (SMEM_FLOATS * 4)   // 130912 B

struct Params {
    const float* u;
    const float* W[9];
    const float* b[9];
    const float* Wr;
    const float* br;
    float* out;
};

// ---- packed f32x2 helpers (Blackwell FFMA2; rounding identical to scalar FFMA) ----
__device__ __forceinline__ unsigned long long pk2(float x, float y) {
    unsigned long long r;
    asm("mov.b64 %0, {%1, %2};" : "=l"(r) : "f"(x), "f"(y));
    return r;
}
__device__ __forceinline__ void upk2(unsigned long long v, float& x, float& y) {
    asm("mov.b64 {%0, %1}, %2;" : "=f"(x), "=f"(y) : "l"(v));
}
__device__ __forceinline__ unsigned long long fma2(unsigned long long a,
                                                   unsigned long long b,
                                                   unsigned long long c) {
    unsigned long long d;
    asm("fma.rn.f32x2 %0, %1, %2, %3;" : "=l"(d) : "l"(a), "l"(b), "l"(c));
    return d;
}

__device__ __forceinline__ void cpy_sh(float* dst, const float* __restrict__ src, int n) {
    for (int k = threadIdx.x; k < n; k += NT) dst[k] = src[k];
}

// ---- packed layer: lane = (og = tid>>4, b = tid&15); weights broadcast in warp ----
// TO even. out[b][o0..o0+TO) = act( in[b][:]@W + bias )
template<int FI, int FO, int TO, bool CLIP>
__device__ __forceinline__ void layerP(const float* __restrict__ W,
                                       const float* __restrict__ bias,
                                       const float* __restrict__ in,
                                       float* __restrict__ out) {
    constexpr int OG = FO / TO;          // output groups (<= 16)
    constexpr int NP = TO / 2;           // f32x2 pairs
    const int og = threadIdx.x >> 4;
    const int b  = threadIdx.x & 15;
    if (OG == 16 || og < OG) {
        const int o0 = og * TO;
        const float* inp = in + b * SBUF;
        unsigned long long acc[NP];
#pragma unroll
        for (int j = 0; j < NP; ++j) {
            float2 bv = *(const float2*)(bias + o0 + 2 * j);
            acc[j] = pk2(bv.x, bv.y);
        }
#pragma unroll
        for (int i = 0; i < FI; ++i) {
            float a = inp[i];
            unsigned long long aa = pk2(a, a);
            const unsigned long long* wr =
                (const unsigned long long*)(W + i * FO + o0);
#pragma unroll
            for (int j = 0; j < NP; ++j)
                acc[j] = fma2(aa, wr[j], acc[j]);
        }
#pragma unroll
        for (int j = 0; j < NP; ++j) {
            float lo, hi;
            upk2(acc[j], lo, hi);
            if (CLIP) {
                lo = fminf(fmaxf(lo, 0.0f), 6.0f);
                hi = fminf(fmaxf(hi, 0.0f), 6.0f);
            }
            *(float2*)(out + b * SBUF + o0 + 2 * j) = make_float2(lo, hi);
        }
    }
}

// ---- scalar layer for TO==1 (L6: 32->16, L7: 16->8) ----
template<int FI, int FO, bool CLIP>
__device__ __forceinline__ void layerS(const float* __restrict__ W,
                                       const float* __restrict__ bias,
                                       const float* __restrict__ in,
                                       float* __restrict__ out) {
    const int og = threadIdx.x >> 4;
    const int b  = threadIdx.x & 15;
    if (FO == 16 || og < FO) {
        const float* inp = in + b * SBUF;
        float acc = bias[og];
#pragma unroll
        for (int i = 0; i < FI; ++i)
            acc = fmaf(inp[i], W[i * FO + og], acc);
        if (CLIP) acc = fminf(fmaxf(acc, 0.0f), 6.0f);
        out[b * SBUF + og] = acc;
    }
}

__global__ void __launch_bounds__(NT, 1) worldnet_kernel(Params p) {
    extern __shared__ float sh[];
    const int tid = threadIdx.x;
    const int b0 = blockIdx.x * BT;

    // ---- one-time weight/bias staging ----
    cpy_sh(sh + OW0, p.W[0], 154 * 16);
    cpy_sh(sh + OW1, p.W[1], 16 * 32);
    cpy_sh(sh + OW2, p.W[2], 32 * 64);
    cpy_sh(sh + OW3, p.W[3], 64 * 128);
    cpy_sh(sh + OW4, p.W[4], 128 * 64);
    cpy_sh(sh + OW5, p.W[5], 64 * 32);
    cpy_sh(sh + OW6, p.W[6], 32 * 16);
    cpy_sh(sh + OW7, p.W[7], 16 * 8);
    for (int k = tid; k < 8 * 128; k += NT) {            // W8 padded 8x128
        int i = k >> 7, o = k & 127;
        sh[OW8 + k] = (o < STATE) ? p.W[8][i * STATE + o] : 0.0f;
    }
    for (int k = tid; k < 348; k += NT)                   // Wr padded
        sh[OWR + k] = (k < STATE * 3) ? p.Wr[k] : 0.0f;
    cpy_sh(sh + OB0, p.b[0], 16);
    cpy_sh(sh + OB1, p.b[1], 32);
    cpy_sh(sh + OB2, p.b[2], 64);
    cpy_sh(sh + OB3, p.b[3], 128);
    cpy_sh(sh + OB4, p.b[4], 64);
    cpy_sh(sh + OB5, p.b[5], 32);
    cpy_sh(sh + OB6, p.b[6], 16);
    cpy_sh(sh + OB7, p.b[7], 8);
    for (int k = tid; k < 128; k += NT)
        sh[OB8 + k] = (k < STATE) ? p.b[8][k] : 0.0f;
    for (int k = tid; k < 4; k += NT)
        sh[OBR + k] = (k < 3) ? p.br[k] : 0.0f;

    // ---- init x0 = u[:, 0, :STATE] ----
    for (int k = tid; k < BT * STATE; k += NT) {
        int b = k / STATE, i = k - b * STATE;
        sh[OXS + b * SX + i] = p.u[(size_t)(b0 + b) * T_STEPS * CIN + i];
    }
    __syncthreads();

    // ---- time loop ----
    for (int t = 0; t < T_STEPS; ++t) {
        // stage actions a_t
        for (int k = tid; k < BT * ACT; k += NT) {
            int b = k / ACT, j = k - b * ACT;
            sh[OAB + b * SA + j] =
                p.u[((size_t)(b0 + b) * T_STEPS + t) * CIN + STATE + j];
        }
        // out[:, t, 0:STATE] = x_t
        for (int k = tid; k < BT * STATE; k += NT) {
            int b = k / STATE, i = k - b * STATE;
            p.out[((size_t)(b0 + b) * T_STEPS + t) * COUT + i] = sh[OXS + b * SX + i];
        }
        __syncthreads();

        // ---- L0: concat(x,a)[154] -> 16, clip. scalar, og = neuron ----
        {
            const float* W = sh + OW0;
            const int og = tid >> 4;
            const int b  = tid & 15;
            float acc = sh[OB0 + og];
            const float* xr = sh + OXS + b * SX;
#pragma unroll
            for (int i = 0; i < STATE; ++i)
                acc = fmaf(xr[i], W[i * 16 + og], acc);
            const float* ar = sh + OAB + b * SA;
#pragma unroll
            for (int j = 0; j < ACT; ++j)
                acc = fmaf(ar[j], W[(STATE + j) * 16 + og], acc);
            acc = fminf(fmaxf(acc, 0.0f), 6.0f);
            sh[OBUFB + b * SBUF + og] = acc;
        }
        __syncthreads();

        layerP<16, 32, 2, true >(sh + OW1, sh + OB1, sh + OBUFB, sh + OBUFA); __syncthreads();
        layerP<32, 64, 4, true >(sh + OW2, sh + OB2, sh + OBUFA, sh + OBUFB); __syncthreads();
        layerP<64, 128, 8, true >(sh + OW3, sh + OB3, sh + OBUFB, sh + OBUFA); __syncthreads();
        layerP<128, 64, 4, true >(sh + OW4, sh + OB4, sh + OBUFA, sh + OBUFB); __syncthreads();
        layerP<64, 32, 2, true >(sh + OW5, sh + OB5, sh + OBUFB, sh + OBUFA); __syncthreads();
        layerS<32, 16, true >(sh + OW6, sh + OB6, sh + OBUFA, sh + OBUFB); __syncthreads();
        layerS<16, 8, true >(sh + OW7, sh + OB7, sh + OBUFB, sh + OBUFA); __syncthreads();
        layerP<8, 128, 8, false>(sh + OW8, sh + OB8, sh + OBUFA, sh + OBUFB); __syncthreads();

        // ---- residual: x <- x + delta ----
        for (int k = tid; k < BT * STATE; k += NT) {
            int b = k / STATE, i = k - b * STATE;
            sh[OXS + b * SX + i] += sh[OBUFB + b * SBUF + i];
        }
        __syncthreads();

        // ---- reward from x_{t+1}: 16 lanes per item ----
        {
            int b = tid >> 4;
            int l = tid & 15;
            float p0 = 0.f, p1 = 0.f, p2 = 0.f;
            const float* xr = sh + OXS + b * SX;
            const float* Wr = sh + OWR;
#pragma unroll
            for (int i = l; i < STATE; i += 16) {
                float v = xr[i];
                p0 = fmaf(v, Wr[3 * i + 0], p0);
                p1 = fmaf(v, Wr[3 * i + 1], p1);
                p2 = fmaf(v, Wr[3 * i + 2], p2);
            }
#pragma unroll
            for (int off = 8; off > 0; off >>= 1) {
                p0 += __shfl_down_sync(0xffffffffu, p0, off, 16);
                p1 += __shfl_down_sync(0xffffffffu, p1, off, 16);
                p2 += __shfl_down_sync(0xffffffffu, p2, off, 16);
            }
            if (l == 0) {
                p0 += sh[OBR + 0]; p1 += sh[OBR + 1]; p2 += sh[OBR + 2];
                p.out[((size_t)(b0 + b) * T_STEPS + t) * COUT + STATE] =
                    -sqrtf(p0 * p0 + p1 * p1 + p2 * p2);
            }
        }
        // no barrier needed: next iter reads OXS (done) / writes OAB & gmem
    }
}

extern "C" void kernel_launch(void* const* d_in, const int* in_sizes, int n_in,
                              void* d_out, int out_size) {
    Params p;
    p.u = (const float*)d_in[0];
    for (int i = 0; i < 9; ++i) {
        p.W[i] = (const float*)d_in[1 + 2 * i];
        p.b[i] = (const float*)d_in[2 + 2 * i];
    }
    p.Wr = (const float*)d_in[19];
    p.br = (const float*)d_in[20];
    p.out = (float*)d_out;

    cudaFuncSetAttribute(worldnet_kernel,
                         cudaFuncAttributeMaxDynamicSharedMemorySize, SMEM_BYTES);
    worldnet_kernel<<<2048 / BT, NT, SMEM_BYTES>>>(p);
}

// round 6
// speedup vs baseline: 1.3511x; 1.1505x over previous
#include <cuda_runtime.h>
#include <math.h>

typedef unsigned long long ull;

// ---------------- problem constants ----------------
#define NT       256     // 8 warps
#define BT       16      // batch items per block -> 128 blocks
#define T_STEPS  128
#define STATE    115
#define ACT      39
#define CIN      154
#define COUT     116

// strides (floats). All mult-of-4 for LDS.128 alignment; conflict-free for
// 8-lane phases: bank(word) = (4b + 4c) % 32 patterns tile all 32 banks.
#define SBUF 132
#define SX   132
#define SA   44

// ---------------- shared memory layout (float offsets) ----------------
#define OW0   0          // padded 156*16 = 2496 (rows: 0..114 x, 115 zero, 116..154 act, 155 zero)
#define OW1   2496       // 16*32  = 512
#define OW2   3008       // 32*64  = 2048
#define OW3   5056       // 64*128 = 8192
#define OW4   13248      // 128*64 = 8192
#define OW5   21440      // 64*32  = 2048
#define OW6   23488      // 32*16  = 512
#define OW7   24000      // 16*8   = 128
#define OW8   24128      // padded 8*128 = 1024
#define OWR   25152      // 348 (Wr padded)
#define OB0   25500
#define OB1   25516
#define OB2   25548
#define OB3   25612
#define OB4   25740
#define OB5   25804
#define OB6   25836
#define OB7   25852
#define OB8   25860      // 128 padded
#define OBR   25988      // 4
#define OBUFA 25992      // 16*132 = 2112
#define OBUFB 28104      // 2112
#define OXS   30216      // 16*132 = 2112 (cols 115..131 zero-padded)
#define OAB   32328      // 16*44  = 704 (col 39 zero)
#define SMEM_FLOATS 33032
#define SMEM_BYTES  (SMEM_FLOATS * 4)   // 132128 B

struct Params {
    const float* u;
    const float* W[9];
    const float* b[9];
    const float* Wr;
    const float* br;
    float* out;
};

// ---- packed f32x2 helpers ----
__device__ __forceinline__ ull pk2(float x, float y) {
    ull r; asm("mov.b64 %0, {%1, %2};" : "=l"(r) : "f"(x), "f"(y)); return r;
}
__device__ __forceinline__ void upk2(ull v, float& x, float& y) {
    asm("mov.b64 {%0, %1}, %2;" : "=f"(x), "=f"(y) : "l"(v));
}
__device__ __forceinline__ ull fma2(ull a, ull b, ull c) {
    ull d; asm("fma.rn.f32x2 %0, %1, %2, %3;" : "=l"(d) : "l"(a), "l"(b), "l"(c)); return d;
}

__device__ __forceinline__ void cpy_sh(float* dst, const float* __restrict__ src, int n) {
    for (int k = threadIdx.x; k < n; k += NT) dst[k] = src[k];
}

// ---- vectorized layer ----
// lane = (og = tid>>4, b = tid&15). Weights broadcast within warp.
// TO in {2,4,8}. Acts via float4, weights via ull/ulonglong2.
// RESID: out[b][o] = xs[b][o] + result (no clip); else clipped write to out.
template<int FI, int FO, int TO, bool CLIP, bool RESID>
__device__ __forceinline__ void layerV(const float* __restrict__ W,
                                       const float* __restrict__ bias,
                                       const float* __restrict__ in,
                                       float* __restrict__ out) {
    constexpr int OG = FO / TO;
    constexpr int NP = TO / 2;
    const int og = threadIdx.x >> 4;
    const int b  = threadIdx.x & 15;
    if (OG >= 16 || og < OG) {
        const int o0 = og * TO;
        const float* inp = in + b * SBUF;
        ull acc[NP];
        if constexpr (TO == 2) {
            float2 bv = *(const float2*)(bias + o0);
            acc[0] = pk2(bv.x, bv.y);
        } else {
#pragma unroll
            for (int q = 0; q < NP / 2; ++q) {
                float4 bv = *(const float4*)(bias + o0 + 4 * q);
                acc[2 * q]     = pk2(bv.x, bv.y);
                acc[2 * q + 1] = pk2(bv.z, bv.w);
            }
        }
#pragma unroll
        for (int i4 = 0; i4 < FI / 4; ++i4) {
            float4 av = *(const float4*)(inp + 4 * i4);
            float ae[4] = {av.x, av.y, av.z, av.w};
#pragma unroll
            for (int e = 0; e < 4; ++e) {
                const int i = 4 * i4 + e;
                ull aa = pk2(ae[e], ae[e]);
                const float* wr = W + i * FO + o0;
                if constexpr (TO == 2) {
                    acc[0] = fma2(aa, *(const ull*)wr, acc[0]);
                } else {
#pragma unroll
                    for (int q = 0; q < NP / 2; ++q) {
                        ulonglong2 wv = *((const ulonglong2*)wr + q);
                        acc[2 * q]     = fma2(aa, wv.x, acc[2 * q]);
                        acc[2 * q + 1] = fma2(aa, wv.y, acc[2 * q + 1]);
                    }
                }
            }
        }
        float r[TO];
#pragma unroll
        for (int j = 0; j < NP; ++j) upk2(acc[j], r[2 * j], r[2 * j + 1]);
        if constexpr (CLIP) {
#pragma unroll
            for (int j = 0; j < TO; ++j) r[j] = fminf(fmaxf(r[j], 0.0f), 6.0f);
        }
        float* op = out + b * SBUF + o0;
        if constexpr (RESID) {
#pragma unroll
            for (int q = 0; q < TO / 4; ++q) {
                float4 xv = *(const float4*)(op + 4 * q);
                xv.x += r[4 * q]; xv.y += r[4 * q + 1];
                xv.z += r[4 * q + 2]; xv.w += r[4 * q + 3];
                *(float4*)(op + 4 * q) = xv;
            }
        } else if constexpr (TO == 2) {
            *(float2*)op = make_float2(r[0], r[1]);
        } else {
#pragma unroll
            for (int q = 0; q < TO / 4; ++q)
                *(float4*)(op + 4 * q) = make_float4(r[4 * q], r[4 * q + 1],
                                                     r[4 * q + 2], r[4 * q + 3]);
        }
    }
}

__global__ void __launch_bounds__(NT, 1) worldnet_kernel(Params p) {
    extern __shared__ float sh[];
    const int tid = threadIdx.x;
    const int b0 = blockIdx.x * BT;

    // ---- one-time weight/bias staging ----
    for (int k = tid; k < 156 * 16; k += NT) {            // W0 padded: zero rows 115 & 155
        int r = k >> 4, c = k & 15;
        float v = 0.0f;
        if (r < 115)                 v = p.W[0][r * 16 + c];
        else if (r >= 116 && r < 155) v = p.W[0][(r - 1) * 16 + c];
        sh[OW0 + k] = v;
    }
    cpy_sh(sh + OW1, p.W[1], 16 * 32);
    cpy_sh(sh + OW2, p.W[2], 32 * 64);
    cpy_sh(sh + OW3, p.W[3], 64 * 128);
    cpy_sh(sh + OW4, p.W[4], 128 * 64);
    cpy_sh(sh + OW5, p.W[5], 64 * 32);
    cpy_sh(sh + OW6, p.W[6], 32 * 16);
    cpy_sh(sh + OW7, p.W[7], 16 * 8);
    for (int k = tid; k < 8 * 128; k += NT) {             // W8 padded 8x128
        int i = k >> 7, o = k & 127;
        sh[OW8 + k] = (o < STATE) ? p.W[8][i * STATE + o] : 0.0f;
    }
    for (int k = tid; k < 348; k += NT)                    // Wr padded
        sh[OWR + k] = (k < STATE * 3) ? p.Wr[k] : 0.0f;
    cpy_sh(sh + OB0, p.b[0], 16);
    cpy_sh(sh + OB1, p.b[1], 32);
    cpy_sh(sh + OB2, p.b[2], 64);
    cpy_sh(sh + OB3, p.b[3], 128);
    cpy_sh(sh + OB4, p.b[4], 64);
    cpy_sh(sh + OB5, p.b[5], 32);
    cpy_sh(sh + OB6, p.b[6], 16);
    cpy_sh(sh + OB7, p.b[7], 8);
    for (int k = tid; k < 128; k += NT)
        sh[OB8 + k] = (k < STATE) ? p.b[8][k] : 0.0f;
    for (int k = tid; k < 4; k += NT)
        sh[OBR + k] = (k < 3) ? p.br[k] : 0.0f;

    // ---- init x0 (zero padded cols 115..131), zero OAB col 39 ----
    for (int k = tid; k < BT * SX; k += NT) {
        int b = k / SX, i = k - b * SX;
        sh[OXS + k] = (i < STATE)
            ? p.u[(size_t)(b0 + b) * T_STEPS * CIN + i] : 0.0f;
    }
    for (int k = tid; k < BT; k += NT)
        sh[OAB + k * SA + ACT] = 0.0f;
    __syncthreads();

    // ---- time loop ----
    for (int t = 0; t < T_STEPS; ++t) {
        // stage actions a_t
        for (int k = tid; k < BT * ACT; k += NT) {
            int b = k / ACT, j = k - b * ACT;
            sh[OAB + b * SA + j] =
                p.u[((size_t)(b0 + b) * T_STEPS + t) * CIN + STATE + j];
        }
        // out[:, t, 0:116] = x_t (slot 115 overwritten by reward later this step)
        for (int k = tid; k < BT * 29; k += NT) {
            int b = k / 29, c = k - b * 29;
            float4 v = *(const float4*)(sh + OXS + b * SX + 4 * c);
            *(float4*)(p.out + ((size_t)(b0 + b) * T_STEPS + t) * COUT + 4 * c) = v;
        }
        __syncthreads();

        // ---- L0: concat(x[116],a[40]) -> 16, clip. TO=2, OG=8 ----
        {
            const int og = tid >> 4;
            const int b  = tid & 15;
            if (og < 8) {
                const int o0 = og * 2;
                float2 bv = *(const float2*)(sh + OB0 + o0);
                ull acc = pk2(bv.x, bv.y);
                const float* xr = sh + OXS + b * SX;
#pragma unroll
                for (int i4 = 0; i4 < 29; ++i4) {
                    float4 av = *(const float4*)(xr + 4 * i4);
                    float ae[4] = {av.x, av.y, av.z, av.w};
#pragma unroll
                    for (int e = 0; e < 4; ++e) {
                        ull aa = pk2(ae[e], ae[e]);
                        acc = fma2(aa, *(const ull*)(sh + OW0 + (4 * i4 + e) * 16 + o0), acc);
                    }
                }
                const float* ar = sh + OAB + b * SA;
#pragma unroll
                for (int j4 = 0; j4 < 10; ++j4) {
                    float4 av = *(const float4*)(ar + 4 * j4);
                    float ae[4] = {av.x, av.y, av.z, av.w};
#pragma unroll
                    for (int e = 0; e < 4; ++e) {
                        ull aa = pk2(ae[e], ae[e]);
                        acc = fma2(aa, *(const ull*)(sh + OW0 + (116 + 4 * j4 + e) * 16 + o0), acc);
                    }
                }
                float lo, hi;
                upk2(acc, lo, hi);
                lo = fminf(fmaxf(lo, 0.0f), 6.0f);
                hi = fminf(fmaxf(hi, 0.0f), 6.0f);
                *(float2*)(sh + OBUFB + b * SBUF + o0) = make_float2(lo, hi);
            }
        }
        __syncthreads();

        layerV<16, 32, 2, true, false>(sh + OW1, sh + OB1, sh + OBUFB, sh + OBUFA); __syncthreads();
        layerV<32, 64, 4, true, false>(sh + OW2, sh + OB2, sh + OBUFA, sh + OBUFB); __syncthreads();
        layerV<64, 128, 8, true, false>(sh + OW3, sh + OB3, sh + OBUFB, sh + OBUFA); __syncthreads();
        layerV<128, 64, 4, true, false>(sh + OW4, sh + OB4, sh + OBUFA, sh + OBUFB); __syncthreads();
        layerV<64, 32, 2, true, false>(sh + OW5, sh + OB5, sh + OBUFB, sh + OBUFA); __syncthreads();
        layerV<32, 16, 2, true, false>(sh + OW6, sh + OB6, sh + OBUFA, sh + OBUFB); __syncthreads();
        layerV<16, 8, 2, true, false>(sh + OW7, sh + OB7, sh + OBUFB, sh + OBUFA); __syncthreads();
        // L8 (8 -> 116 padded to 128) fused with residual: XS += delta
        layerV<8, 128, 8, false, true>(sh + OW8, sh + OB8, sh + OBUFA, sh + OXS); __syncthreads();

        // ---- reward from x_{t+1}: 16 lanes per item ----
        {
            int b = tid >> 4;
            int l = tid & 15;
            float p0 = 0.f, p1 = 0.f, p2 = 0.f;
            const float* xr = sh + OXS + b * SX;
            const float* Wr = sh + OWR;
#pragma unroll
            for (int i = l; i < STATE; i += 16) {
                float v = xr[i];
                p0 = fmaf(v, Wr[3 * i + 0], p0);
                p1 = fmaf(v, Wr[3 * i + 1], p1);
                p2 = fmaf(v, Wr[3 * i + 2], p2);
            }
#pragma unroll
            for (int off = 8; off > 0; off >>= 1) {
                p0 += __shfl_down_sync(0xffffffffu, p0, off, 16);
                p1 += __shfl_down_sync(0xffffffffu, p1, off, 16);
                p2 += __shfl_down_sync(0xffffffffu, p2, off, 16);
            }
            if (l == 0) {
                p0 += sh[OBR + 0]; p1 += sh[OBR + 1]; p2 += sh[OBR + 2];
                p.out[((size_t)(b0 + b) * T_STEPS + t) * COUT + STATE] =
                    -sqrtf(p0 * p0 + p1 * p1 + p2 * p2);
            }
        }
        // no barrier: next iter writes OAB / reads OXS (both safe vs reward)
    }
}

extern "C" void kernel_launch(void* const* d_in, const int* in_sizes, int n_in,
                              void* d_out, int out_size) {
    Params p;
    p.u = (const float*)d_in[0];
    for (int i = 0; i < 9; ++i) {
        p.W[i] = (const float*)d_in[1 + 2 * i];
        p.b[i] = (const float*)d_in[2 + 2 * i];
    }
    p.Wr = (const float*)d_in[19];
    p.br = (const float*)d_in[20];
    p.out = (float*)d_out;

    cudaFuncSetAttribute(worldnet_kernel,
                         cudaFuncAttributeMaxDynamicSharedMemorySize, SMEM_BYTES);
    worldnet_kernel<<<2048 / BT, NT, SMEM_BYTES>>>(p);
}